// round 9
// baseline (speedup 1.0000x reference)
#include <cuda_runtime.h>
#include <cuda_bf16.h>
#include <cuda_pipeline.h>
#include <mma.h>
#include <cstdint>

using namespace nvcuda;

#define NNODES 50000
#define MPAD   50048          // 391 * 128
#define EMAX   800000
#define DOUT   256
#define DIN    256

// ---------------------------------------------------------------------------
// Scratch (device globals)
// ---------------------------------------------------------------------------
__device__ float g_h[(size_t)MPAD * DOUT];       // x @ W (fp32, padded rows)
__device__ int   g_degi[NNODES];
__device__ int   g_off[NNODES];
__device__ int   g_cur[NNODES];
__device__ float g_dinv[NNODES];
__device__ int   g_csr[EMAX];
__device__ int   g_bsum[64];
__device__ __nv_bfloat16 g_wt_hi[DOUT * DIN];    // W^T [n][k], k contiguous
__device__ __nv_bfloat16 g_wt_lo[DOUT * DIN];

// ---------------------------------------------------------------------------
// Degree / CSR build
// ---------------------------------------------------------------------------
__global__ void k_zero(int n) {
    int i = blockIdx.x * blockDim.x + threadIdx.x;
    if (i < n) g_degi[i] = 0;
}
__global__ void k_count(const int* __restrict__ dst, int E) {
    int i = blockIdx.x * blockDim.x + threadIdx.x;
    if (i < E) atomicAdd(&g_degi[dst[i]], 1);
}

__global__ __launch_bounds__(1024) void k_scan1(int n) {
    __shared__ int wsum[32];
    int tid = threadIdx.x, lane = tid & 31, wid = tid >> 5;
    int i = blockIdx.x * 1024 + tid;
    int v = (i < n) ? g_degi[i] : 0;
    if (i < n) g_dinv[i] = rsqrtf((float)(v + 1));
    int sc = v;
    #pragma unroll
    for (int o = 1; o < 32; o <<= 1) {
        int t = __shfl_up_sync(0xffffffffu, sc, o);
        if (lane >= o) sc += t;
    }
    if (lane == 31) wsum[wid] = sc;
    __syncthreads();
    if (wid == 0) {
        int s = wsum[lane];
        #pragma unroll
        for (int o = 1; o < 32; o <<= 1) {
            int t = __shfl_up_sync(0xffffffffu, s, o);
            if (lane >= o) s += t;
        }
        wsum[lane] = s;
    }
    __syncthreads();
    int warpoff = (wid > 0) ? wsum[wid - 1] : 0;
    if (i < n) g_off[i] = warpoff + sc - v;
    if (tid == 0) g_bsum[blockIdx.x] = wsum[31];
}

__global__ void k_scan2(int nb) {
    __shared__ int w0tot;
    int t = threadIdx.x, lane = t & 31, wid = t >> 5;
    int v = (t < nb) ? g_bsum[t] : 0;
    int sc = v;
    #pragma unroll
    for (int o = 1; o < 32; o <<= 1) {
        int x = __shfl_up_sync(0xffffffffu, sc, o);
        if (lane >= o) sc += x;
    }
    if (wid == 0 && lane == 31) w0tot = sc;
    __syncthreads();
    int excl = sc - v + (wid ? w0tot : 0);
    if (t < nb) g_bsum[t] = excl;
}

__global__ __launch_bounds__(1024) void k_scan3(int n) {
    int i = blockIdx.x * 1024 + threadIdx.x;
    if (i >= n) return;
    int o = g_off[i] + g_bsum[blockIdx.x];
    g_off[i] = o;
    g_cur[i] = o;
}

__global__ void k_fill(const int* __restrict__ src,
                       const int* __restrict__ dst, int E) {
    int i = blockIdx.x * blockDim.x + threadIdx.x;
    if (i >= E) return;
    int d = dst[i];
    int pos = atomicAdd(&g_cur[d], 1);
    g_csr[pos] = src[i];
}

// ---------------------------------------------------------------------------
// W^T hi/lo split
// ---------------------------------------------------------------------------
__global__ void k_wt(const float* __restrict__ W) {
    int i = blockIdx.x * blockDim.x + threadIdx.x;   // n*256 + k
    if (i >= DIN * DOUT) return;
    int n = i >> 8, k = i & 255;
    float w = W[k * DOUT + n];
    __nv_bfloat16 hi = __float2bfloat16_rn(w);
    g_wt_hi[i] = hi;
    g_wt_lo[i] = __float2bfloat16_rn(w - __bfloat162float(hi));
}

// ---------------------------------------------------------------------------
// WMMA GEMM with fused A split.
// CTA 128(M) x 128(N), 8 warps 4x2, warp tile 32x64. BK=32, 8 chunks.
// A: fp32 staged via cp.async (2 stages), converted to bf16 hi/lo smem
//    (single buffer) at the top of each chunk. Rows >= M clamp to M-1
//    (garbage lands in padded g_h rows never read by k_node).
// B: bf16 hi/lo staged via cp.async (2 stages) from g_wt.
// Smem: fp32 A 2x18KB + bf16 A 2x10KB + B 4x10KB = 96 KB dynamic.
// ---------------------------------------------------------------------------
#define LDS   40                          // bf16 array stride (elements)
#define LDSF  36                          // fp32 A stage stride (floats)
#define SZ_SF (128 * LDSF)                // floats per fp32 stage
#define SZ_BA (128 * LDS)                 // bf16 elems per array
// byte offsets into dynamic smem
#define OFF_SF   0
#define OFF_AHI  (2 * SZ_SF * 4)                      // 36864
#define OFF_ALO  (OFF_AHI + SZ_BA * 2)                // +10240
#define OFF_B    (OFF_ALO + SZ_BA * 2)                // 57344
#define SMEM_BYTES (OFF_B + 4 * SZ_BA * 2)            // 98304 = 96 KB

__global__ __launch_bounds__(256) void k_gemm_wmma(const float* __restrict__ x,
                                                   int M) {
    extern __shared__ __align__(16) char smraw[];
    float* sF = (float*)(smraw + OFF_SF);                  // [2][128*LDSF]
    __nv_bfloat16* sA_hi = (__nv_bfloat16*)(smraw + OFF_AHI);
    __nv_bfloat16* sA_lo = (__nv_bfloat16*)(smraw + OFF_ALO);
    __nv_bfloat16* sB = (__nv_bfloat16*)(smraw + OFF_B);   // [2 stages][hi,lo]

    const int tid = threadIdx.x;
    const int w = tid >> 5;
    const int warp_m = w & 3;
    const int warp_n = w >> 2;
    const int Rbase = blockIdx.x * 128;
    const int Nbase = blockIdx.y * 128;

    // A fp32 staging: 1024 16B-chunks per stage, 4 per thread
    // chunk idx c: row = c>>3, seg = c&7 (4 floats each)
    auto prefetch_A = [&](int kc, int stage) {
        float* dst = sF + stage * SZ_SF;
        #pragma unroll
        for (int j = 0; j < 4; j++) {
            int c = tid * 4 + j;
            int r = c >> 3, seg = c & 7;
            int gr = Rbase + r; if (gr >= M) gr = M - 1;   // clamp (no OOB)
            __pipeline_memcpy_async(dst + r * LDSF + seg * 4,
                x + (size_t)gr * DIN + kc * 32 + seg * 4, 16);
        }
    };
    // B staging: 512 16B-chunks per array, 2 per thread
    const int idx0 = tid * 2;
    const int br0 = idx0 >> 2, bs0 = idx0 & 3;
    const int br1 = (idx0 + 1) >> 2, bs1 = (idx0 + 1) & 3;
    auto prefetch_B = [&](int kc, int stage) {
        __nv_bfloat16* dhi = sB + stage * 2 * SZ_BA;
        __nv_bfloat16* dlo = dhi + SZ_BA;
        __pipeline_memcpy_async(dhi + br0 * LDS + bs0 * 8,
            (const uint4*)g_wt_hi + (size_t)(Nbase + br0) * 32 + kc * 4 + bs0, 16);
        __pipeline_memcpy_async(dhi + br1 * LDS + bs1 * 8,
            (const uint4*)g_wt_hi + (size_t)(Nbase + br1) * 32 + kc * 4 + bs1, 16);
        __pipeline_memcpy_async(dlo + br0 * LDS + bs0 * 8,
            (const uint4*)g_wt_lo + (size_t)(Nbase + br0) * 32 + kc * 4 + bs0, 16);
        __pipeline_memcpy_async(dlo + br1 * LDS + bs1 * 8,
            (const uint4*)g_wt_lo + (size_t)(Nbase + br1) * 32 + kc * 4 + bs1, 16);
    };

    wmma::fragment<wmma::accumulator, 16, 16, 16, float> acc[2][4];
    #pragma unroll
    for (int mi = 0; mi < 2; mi++)
        #pragma unroll
        for (int ni = 0; ni < 4; ni++)
            wmma::fill_fragment(acc[mi][ni], 0.0f);

    prefetch_A(0, 0);
    prefetch_B(0, 0);
    __pipeline_commit();

    for (int kc = 0; kc < 8; kc++) {
        if (kc < 7) {
            prefetch_A(kc + 1, (kc + 1) & 1);
            prefetch_B(kc + 1, (kc + 1) & 1);
            __pipeline_commit();
        }
        __pipeline_wait_prior(kc < 7 ? 1 : 0);
        __syncthreads();   // stage ready; also: prior MMA done -> sA reusable

        // convert fp32 A chunk -> bf16 hi/lo (thread: row=tid>>1, half=tid&1)
        {
            const float* fsrc = sF + (kc & 1) * SZ_SF + (tid >> 1) * LDSF + (tid & 1) * 16;
            uint32_t* dh = (uint32_t*)(sA_hi + (tid >> 1) * LDS + (tid & 1) * 16);
            uint32_t* dl = (uint32_t*)(sA_lo + (tid >> 1) * LDS + (tid & 1) * 16);
            #pragma unroll
            for (int j = 0; j < 8; j++) {
                float f0 = fsrc[j * 2], f1 = fsrc[j * 2 + 1];
                __nv_bfloat16 h0 = __float2bfloat16_rn(f0);
                __nv_bfloat16 h1 = __float2bfloat16_rn(f1);
                __nv_bfloat16 l0 = __float2bfloat16_rn(f0 - __bfloat162float(h0));
                __nv_bfloat16 l1 = __float2bfloat16_rn(f1 - __bfloat162float(h1));
                dh[j] = ((uint32_t)__bfloat16_as_ushort(h1) << 16) | __bfloat16_as_ushort(h0);
                dl[j] = ((uint32_t)__bfloat16_as_ushort(l1) << 16) | __bfloat16_as_ushort(l0);
            }
        }
        __syncthreads();

        __nv_bfloat16* sB_hi = sB + (kc & 1) * 2 * SZ_BA;
        __nv_bfloat16* sB_lo = sB_hi + SZ_BA;

        #pragma unroll
        for (int kk = 0; kk < 32; kk += 16) {
            wmma::fragment<wmma::matrix_a, 16, 16, 16, __nv_bfloat16, wmma::row_major> ah[2], al[2];
            #pragma unroll
            for (int mi = 0; mi < 2; mi++) {
                wmma::load_matrix_sync(ah[mi], sA_hi + (warp_m * 32 + mi * 16) * LDS + kk, LDS);
                wmma::load_matrix_sync(al[mi], sA_lo + (warp_m * 32 + mi * 16) * LDS + kk, LDS);
            }
            wmma::fragment<wmma::matrix_b, 16, 16, 16, __nv_bfloat16, wmma::col_major> bf[4];
            #pragma unroll
            for (int ni = 0; ni < 4; ni++)
                wmma::load_matrix_sync(bf[ni], sB_hi + (warp_n * 64 + ni * 16) * LDS + kk, LDS);
            #pragma unroll
            for (int mi = 0; mi < 2; mi++)
                #pragma unroll
                for (int ni = 0; ni < 4; ni++) {
                    wmma::mma_sync(acc[mi][ni], ah[mi], bf[ni], acc[mi][ni]);
                    wmma::mma_sync(acc[mi][ni], al[mi], bf[ni], acc[mi][ni]);
                }
            #pragma unroll
            for (int ni = 0; ni < 4; ni++)
                wmma::load_matrix_sync(bf[ni], sB_lo + (warp_n * 64 + ni * 16) * LDS + kk, LDS);
            #pragma unroll
            for (int mi = 0; mi < 2; mi++)
                #pragma unroll
                for (int ni = 0; ni < 4; ni++)
                    wmma::mma_sync(acc[mi][ni], ah[mi], bf[ni], acc[mi][ni]);
        }
    }

    #pragma unroll
    for (int mi = 0; mi < 2; mi++) {
        int row = Rbase + warp_m * 32 + mi * 16;
        #pragma unroll
        for (int ni = 0; ni < 4; ni++) {
            int col = Nbase + warp_n * 64 + ni * 16;
            wmma::store_matrix_sync(g_h + (size_t)row * DOUT + col,
                                    acc[mi][ni], DOUT, wmma::mem_row_major);
        }
    }
}

// ---------------------------------------------------------------------------
// Node kernel: one warp per destination node, 4-edge unroll
// ---------------------------------------------------------------------------
#define FMA4(acc, v, s) \
    acc.x = fmaf((v).x, (s), acc.x); acc.y = fmaf((v).y, (s), acc.y); \
    acc.z = fmaf((v).z, (s), acc.z); acc.w = fmaf((v).w, (s), acc.w)

__global__ __launch_bounds__(256) void k_node(float* __restrict__ out,
                                              const float* __restrict__ b,
                                              const float* __restrict__ gamma,
                                              const float* __restrict__ beta,
                                              const float* __restrict__ mean,
                                              const float* __restrict__ var,
                                              int n) {
    int warp = (blockIdx.x * blockDim.x + threadIdx.x) >> 5;
    int lane = threadIdx.x & 31;
    if (warp >= n) return;

    int node = warp;
    int start = g_off[node];
    int end   = start + g_degi[node];

    float4 acc0 = make_float4(0.f, 0.f, 0.f, 0.f);
    float4 acc1 = make_float4(0.f, 0.f, 0.f, 0.f);

    int e = start;
    for (; e + 3 < end; e += 4) {
        int s0 = g_csr[e + 0], s1 = g_csr[e + 1];
        int s2 = g_csr[e + 2], s3 = g_csr[e + 3];
        float w0 = g_dinv[s0], w1 = g_dinv[s1];
        float w2 = g_dinv[s2], w3 = g_dinv[s3];
        const float4* r0 = (const float4*)(g_h + (size_t)s0 * DOUT);
        const float4* r1 = (const float4*)(g_h + (size_t)s1 * DOUT);
        const float4* r2 = (const float4*)(g_h + (size_t)s2 * DOUT);
        const float4* r3 = (const float4*)(g_h + (size_t)s3 * DOUT);
        float4 a0 = __ldg(r0 + lane),      a1 = __ldg(r0 + lane + 32);
        float4 b0 = __ldg(r1 + lane),      b1 = __ldg(r1 + lane + 32);
        float4 c0 = __ldg(r2 + lane),      c1 = __ldg(r2 + lane + 32);
        float4 d0 = __ldg(r3 + lane),      d1 = __ldg(r3 + lane + 32);
        FMA4(acc0, a0, w0); FMA4(acc1, a1, w0);
        FMA4(acc0, b0, w1); FMA4(acc1, b1, w1);
        FMA4(acc0, c0, w2); FMA4(acc1, c1, w2);
        FMA4(acc0, d0, w3); FMA4(acc1, d1, w3);
    }
    for (; e < end; e++) {
        int s0 = g_csr[e];
        float w0 = g_dinv[s0];
        const float4* r0 = (const float4*)(g_h + (size_t)s0 * DOUT);
        float4 a0 = __ldg(r0 + lane), a1 = __ldg(r0 + lane + 32);
        FMA4(acc0, a0, w0); FMA4(acc1, a1, w0);
    }

    float di = g_dinv[node];
    const float4* hr = (const float4*)(g_h + (size_t)node * DOUT);
    float4 h0 = __ldg(hr + lane), h1 = __ldg(hr + lane + 32);
    FMA4(acc0, h0, di); FMA4(acc1, h1, di);
    acc0.x *= di; acc0.y *= di; acc0.z *= di; acc0.w *= di;
    acc1.x *= di; acc1.y *= di; acc1.z *= di; acc1.w *= di;

    #pragma unroll
    for (int half = 0; half < 2; half++) {
        int c4 = lane + half * 32;
        float4 bv = ((const float4*)b)[c4];
        float4 gv = ((const float4*)gamma)[c4];
        float4 tv = ((const float4*)beta)[c4];
        float4 mv = ((const float4*)mean)[c4];
        float4 vv = ((const float4*)var)[c4];
        float4 a = half ? acc1 : acc0;
        float4 r;
        float sx = gv.x * rsqrtf(vv.x + 1e-5f);
        float sy = gv.y * rsqrtf(vv.y + 1e-5f);
        float sz = gv.z * rsqrtf(vv.z + 1e-5f);
        float sw = gv.w * rsqrtf(vv.w + 1e-5f);
        r.x = fmaxf(fmaf(a.x + bv.x - mv.x, sx, tv.x), 0.f);
        r.y = fmaxf(fmaf(a.y + bv.y - mv.y, sy, tv.y), 0.f);
        r.z = fmaxf(fmaf(a.z + bv.z - mv.z, sz, tv.z), 0.f);
        r.w = fmaxf(fmaf(a.w + bv.w - mv.w, sw, tv.w), 0.f);
        ((float4*)(out + (size_t)node * DOUT))[c4] = r;
    }
}

// ---------------------------------------------------------------------------
// Two-stream DAG:
//   main:  wt -> gemm -----------------------------------+-> node
//   s2:    zero -> count -> scan1/2/3 -> fill -----------+
// Launch order keeps gemm at slot #4 for the ncu profile.
// ---------------------------------------------------------------------------
extern "C" void kernel_launch(void* const* d_in, const int* in_sizes, int n_in,
                              void* d_out, int out_size) {
    const float* x      = (const float*)d_in[0];
    const int*   ei     = (const int*)d_in[1];   // int32 (jax x64 disabled)
    const float* W      = (const float*)d_in[2];
    const float* b      = (const float*)d_in[3];
    const float* gamma  = (const float*)d_in[4];
    const float* beta   = (const float*)d_in[5];
    const float* rmean  = (const float*)d_in[6];
    const float* rvar   = (const float*)d_in[7];
    float* out = (float*)d_out;

    int N = in_sizes[0] / DIN;     // 50000
    int E = in_sizes[1] / 2;       // 800000
    const int* src = ei;
    const int* dst = ei + E;
    int nb = (N + 1023) / 1024;

    static cudaStream_t s2;
    static cudaEvent_t ev_fork, ev_join;
    static bool init_done = false;
    if (!init_done) {
        cudaFuncSetAttribute(k_gemm_wmma,
                             cudaFuncAttributeMaxDynamicSharedMemorySize,
                             SMEM_BYTES);
        cudaStreamCreateWithFlags(&s2, cudaStreamNonBlocking);
        cudaEventCreateWithFlags(&ev_fork, cudaEventDisableTiming);
        cudaEventCreateWithFlags(&ev_join, cudaEventDisableTiming);
        init_done = true;
    }

    // fork
    cudaEventRecord(ev_fork, 0);
    cudaStreamWaitEvent(s2, ev_fork, 0);

    k_wt<<<(DIN * DOUT + 255) / 256, 256>>>(W);                    // launch 1
    k_zero<<<(N + 255) / 256, 256, 0, s2>>>(N);                    // launch 2
    k_count<<<(E + 255) / 256, 256, 0, s2>>>(dst, E);              // launch 3

    dim3 ggrid(MPAD / 128, DOUT / 128);
    k_gemm_wmma<<<ggrid, 256, SMEM_BYTES>>>(x, N);                 // launch 4

    k_scan1<<<nb, 1024, 0, s2>>>(N);
    k_scan2<<<1, 64, 0, s2>>>(nb);
    k_scan3<<<nb, 1024, 0, s2>>>(N);
    k_fill<<<(E + 255) / 256, 256, 0, s2>>>(src, dst, E);

    // join
    cudaEventRecord(ev_join, s2);
    cudaStreamWaitEvent(0, ev_join, 0);

    long long nthreads = (long long)N * 32;
    k_node<<<(int)((nthreads + 255) / 256), 256>>>(out, b, gamma, beta,
                                                   rmean, rvar, N);
}

// round 11
// speedup vs baseline: 1.0652x; 1.0652x over previous
#include <cuda_runtime.h>
#include <cuda_bf16.h>
#include <cuda_pipeline.h>
#include <mma.h>
#include <cstdint>

using namespace nvcuda;

#define NNODES 50000
#define MPAD   50048          // 391 * 128
#define EMAX   800000
#define DOUT   256
#define DIN    256

// ---------------------------------------------------------------------------
// Scratch (device globals)
// ---------------------------------------------------------------------------
__device__ float g_h[(size_t)MPAD * DOUT];       // x @ W (fp32, padded rows)
__device__ int   g_degi[NNODES];
__device__ int   g_off[NNODES];
__device__ int   g_cur[NNODES];
__device__ float g_dinv[NNODES];
__device__ int   g_csr[EMAX];
__device__ int   g_bsum[64];
__device__ __nv_bfloat16 g_wt_hi[DOUT * DIN];    // W^T [n][k], k contiguous
__device__ __nv_bfloat16 g_wt_lo[DOUT * DIN];

// ---------------------------------------------------------------------------
// Degree / CSR build
// ---------------------------------------------------------------------------
__global__ void k_zero(int n) {
    int i = blockIdx.x * blockDim.x + threadIdx.x;
    if (i < n) g_degi[i] = 0;
}
__global__ void k_count(const int* __restrict__ dst, int E) {
    int i = blockIdx.x * blockDim.x + threadIdx.x;
    if (i < E) atomicAdd(&g_degi[dst[i]], 1);
}

__global__ __launch_bounds__(1024) void k_scan1(int n) {
    __shared__ int wsum[32];
    int tid = threadIdx.x, lane = tid & 31, wid = tid >> 5;
    int i = blockIdx.x * 1024 + tid;
    int v = (i < n) ? g_degi[i] : 0;
    if (i < n) g_dinv[i] = rsqrtf((float)(v + 1));
    int sc = v;
    #pragma unroll
    for (int o = 1; o < 32; o <<= 1) {
        int t = __shfl_up_sync(0xffffffffu, sc, o);
        if (lane >= o) sc += t;
    }
    if (lane == 31) wsum[wid] = sc;
    __syncthreads();
    if (wid == 0) {
        int s = wsum[lane];
        #pragma unroll
        for (int o = 1; o < 32; o <<= 1) {
            int t = __shfl_up_sync(0xffffffffu, s, o);
            if (lane >= o) s += t;
        }
        wsum[lane] = s;
    }
    __syncthreads();
    int warpoff = (wid > 0) ? wsum[wid - 1] : 0;
    if (i < n) g_off[i] = warpoff + sc - v;
    if (tid == 0) g_bsum[blockIdx.x] = wsum[31];
}

__global__ void k_scan2(int nb) {
    __shared__ int w0tot;
    int t = threadIdx.x, lane = t & 31, wid = t >> 5;
    int v = (t < nb) ? g_bsum[t] : 0;
    int sc = v;
    #pragma unroll
    for (int o = 1; o < 32; o <<= 1) {
        int x = __shfl_up_sync(0xffffffffu, sc, o);
        if (lane >= o) sc += x;
    }
    if (wid == 0 && lane == 31) w0tot = sc;
    __syncthreads();
    int excl = sc - v + (wid ? w0tot : 0);
    if (t < nb) g_bsum[t] = excl;
}

__global__ __launch_bounds__(1024) void k_scan3(int n) {
    int i = blockIdx.x * 1024 + threadIdx.x;
    if (i >= n) return;
    int o = g_off[i] + g_bsum[blockIdx.x];
    g_off[i] = o;
    g_cur[i] = o;
}

__global__ void k_fill(const int* __restrict__ src,
                       const int* __restrict__ dst, int E) {
    int i = blockIdx.x * blockDim.x + threadIdx.x;
    if (i >= E) return;
    int d = dst[i];
    int pos = atomicAdd(&g_cur[d], 1);
    g_csr[pos] = src[i];
}

// ---------------------------------------------------------------------------
// W^T hi/lo split
// ---------------------------------------------------------------------------
__global__ void k_wt(const float* __restrict__ W) {
    int i = blockIdx.x * blockDim.x + threadIdx.x;   // n*256 + k
    if (i >= DIN * DOUT) return;
    int n = i >> 8, k = i & 255;
    float w = W[k * DOUT + n];
    __nv_bfloat16 hi = __float2bfloat16_rn(w);
    g_wt_hi[i] = hi;
    g_wt_lo[i] = __float2bfloat16_rn(w - __bfloat162float(hi));
}

// ---------------------------------------------------------------------------
// WMMA GEMM with fused A split, double-buffered cp.async, 2 CTAs/SM.
// RACE FIX vs R9/R10: __syncthreads() at END of each kc iteration, so all
// warps finish reading stage (kc&1) before any thread issues next-next-stage
// cp.async writes into the same buffers.
// ---------------------------------------------------------------------------
#define LDS   40                          // bf16 array stride (elements)
#define LDSF  36                          // fp32 A stage stride (floats)
#define SZ_SF (128 * LDSF)                // floats per fp32 stage
#define SZ_BA (128 * LDS)                 // bf16 elems per array
#define OFF_SF   0
#define OFF_AHI  (2 * SZ_SF * 4)                      // 36864
#define OFF_ALO  (OFF_AHI + SZ_BA * 2)                // +10240
#define OFF_B    (OFF_ALO + SZ_BA * 2)                // 57344
#define SMEM_BYTES (OFF_B + 4 * SZ_BA * 2)            // 98304 = 96 KB

__global__ __launch_bounds__(256, 2) void k_gemm_wmma(const float* __restrict__ x,
                                                      int M) {
    extern __shared__ __align__(16) char smraw[];
    float* sF = (float*)(smraw + OFF_SF);                  // [2][128*LDSF]
    __nv_bfloat16* sA_hi = (__nv_bfloat16*)(smraw + OFF_AHI);
    __nv_bfloat16* sA_lo = (__nv_bfloat16*)(smraw + OFF_ALO);
    __nv_bfloat16* sB = (__nv_bfloat16*)(smraw + OFF_B);   // [2 stages][hi,lo]

    const int tid = threadIdx.x;
    const int w = tid >> 5;
    const int warp_m = w & 3;
    const int warp_n = w >> 2;
    const int Rbase = blockIdx.x * 128;
    const int Nbase = blockIdx.y * 128;

    // A staging: thread = (row tid>>1, half tid&1), 16 contiguous floats
    int garow = Rbase + (tid >> 1);
    if (garow >= M) garow = M - 1;                         // clamp, no OOB
    const float* ga_base = x + (size_t)garow * DIN + (tid & 1) * 16;
    float* sf_base = sF + (tid >> 1) * LDSF + (tid & 1) * 16;

    auto prefetch_A = [&](int kc, int stage) {
        float* dst = sf_base + stage * SZ_SF;
        const float* src = ga_base + kc * 32;
        #pragma unroll
        for (int j = 0; j < 4; j++)
            __pipeline_memcpy_async(dst + j * 4, src + j * 4, 16);
    };
    const int idx0 = tid * 2;
    const int br0 = idx0 >> 2, bs0 = idx0 & 3;
    const int br1 = (idx0 + 1) >> 2, bs1 = (idx0 + 1) & 3;
    auto prefetch_B = [&](int kc, int stage) {
        __nv_bfloat16* dhi = sB + stage * 2 * SZ_BA;
        __nv_bfloat16* dlo = dhi + SZ_BA;
        __pipeline_memcpy_async(dhi + br0 * LDS + bs0 * 8,
            (const uint4*)g_wt_hi + (size_t)(Nbase + br0) * 32 + kc * 4 + bs0, 16);
        __pipeline_memcpy_async(dhi + br1 * LDS + bs1 * 8,
            (const uint4*)g_wt_hi + (size_t)(Nbase + br1) * 32 + kc * 4 + bs1, 16);
        __pipeline_memcpy_async(dlo + br0 * LDS + bs0 * 8,
            (const uint4*)g_wt_lo + (size_t)(Nbase + br0) * 32 + kc * 4 + bs0, 16);
        __pipeline_memcpy_async(dlo + br1 * LDS + bs1 * 8,
            (const uint4*)g_wt_lo + (size_t)(Nbase + br1) * 32 + kc * 4 + bs1, 16);
    };

    wmma::fragment<wmma::accumulator, 16, 16, 16, float> acc[2][4];
    #pragma unroll
    for (int mi = 0; mi < 2; mi++)
        #pragma unroll
        for (int ni = 0; ni < 4; ni++)
            wmma::fill_fragment(acc[mi][ni], 0.0f);

    prefetch_A(0, 0);
    prefetch_B(0, 0);
    __pipeline_commit();

    for (int kc = 0; kc < 8; kc++) {
        if (kc < 7) {
            prefetch_A(kc + 1, (kc + 1) & 1);
            prefetch_B(kc + 1, (kc + 1) & 1);
            __pipeline_commit();
        }
        __pipeline_wait_prior(kc < 7 ? 1 : 0);
        __syncthreads();   // stage (kc&1) data ready for all warps

        // convert fp32 A chunk -> bf16 hi/lo (row=tid>>1, half=tid&1)
        {
            const float* fsrc = sF + (kc & 1) * SZ_SF + (tid >> 1) * LDSF + (tid & 1) * 16;
            uint32_t* dh = (uint32_t*)(sA_hi + (tid >> 1) * LDS + (tid & 1) * 16);
            uint32_t* dl = (uint32_t*)(sA_lo + (tid >> 1) * LDS + (tid & 1) * 16);
            #pragma unroll
            for (int j = 0; j < 8; j++) {
                float f0 = fsrc[j * 2], f1 = fsrc[j * 2 + 1];
                __nv_bfloat16 h0 = __float2bfloat16_rn(f0);
                __nv_bfloat16 h1 = __float2bfloat16_rn(f1);
                __nv_bfloat16 l0 = __float2bfloat16_rn(f0 - __bfloat162float(h0));
                __nv_bfloat16 l1 = __float2bfloat16_rn(f1 - __bfloat162float(h1));
                dh[j] = ((uint32_t)__bfloat16_as_ushort(h1) << 16) | __bfloat16_as_ushort(h0);
                dl[j] = ((uint32_t)__bfloat16_as_ushort(l1) << 16) | __bfloat16_as_ushort(l0);
            }
        }
        __syncthreads();   // converted A visible to all warps

        __nv_bfloat16* sB_hi = sB + (kc & 1) * 2 * SZ_BA;
        __nv_bfloat16* sB_lo = sB_hi + SZ_BA;

        #pragma unroll
        for (int kk = 0; kk < 32; kk += 16) {
            wmma::fragment<wmma::matrix_a, 16, 16, 16, __nv_bfloat16, wmma::row_major> ah[2], al[2];
            #pragma unroll
            for (int mi = 0; mi < 2; mi++) {
                wmma::load_matrix_sync(ah[mi], sA_hi + (warp_m * 32 + mi * 16) * LDS + kk, LDS);
                wmma::load_matrix_sync(al[mi], sA_lo + (warp_m * 32 + mi * 16) * LDS + kk, LDS);
            }
            wmma::fragment<wmma::matrix_b, 16, 16, 16, __nv_bfloat16, wmma::col_major> bf[4];
            #pragma unroll
            for (int ni = 0; ni < 4; ni++)
                wmma::load_matrix_sync(bf[ni], sB_hi + (warp_n * 64 + ni * 16) * LDS + kk, LDS);
            #pragma unroll
            for (int mi = 0; mi < 2; mi++)
                #pragma unroll
                for (int ni = 0; ni < 4; ni++) {
                    wmma::mma_sync(acc[mi][ni], ah[mi], bf[ni], acc[mi][ni]);
                    wmma::mma_sync(acc[mi][ni], al[mi], bf[ni], acc[mi][ni]);
                }
            #pragma unroll
            for (int ni = 0; ni < 4; ni++)
                wmma::load_matrix_sync(bf[ni], sB_lo + (warp_n * 64 + ni * 16) * LDS + kk, LDS);
            #pragma unroll
            for (int mi = 0; mi < 2; mi++)
                #pragma unroll
                for (int ni = 0; ni < 4; ni++)
                    wmma::mma_sync(acc[mi][ni], ah[mi], bf[ni], acc[mi][ni]);
        }
        __syncthreads();   // RACE FIX: all stage reads done before next
                           // iteration's cp.async overwrites this stage
    }

    #pragma unroll
    for (int mi = 0; mi < 2; mi++) {
        int row = Rbase + warp_m * 32 + mi * 16;
        #pragma unroll
        for (int ni = 0; ni < 4; ni++) {
            int col = Nbase + warp_n * 64 + ni * 16;
            wmma::store_matrix_sync(g_h + (size_t)row * DOUT + col,
                                    acc[mi][ni], DOUT, wmma::mem_row_major);
        }
    }
}

// ---------------------------------------------------------------------------
// Node kernel: one warp per destination node, 4-edge unroll
// ---------------------------------------------------------------------------
#define FMA4(acc, v, s) \
    acc.x = fmaf((v).x, (s), acc.x); acc.y = fmaf((v).y, (s), acc.y); \
    acc.z = fmaf((v).z, (s), acc.z); acc.w = fmaf((v).w, (s), acc.w)

__global__ __launch_bounds__(256) void k_node(float* __restrict__ out,
                                              const float* __restrict__ b,
                                              const float* __restrict__ gamma,
                                              const float* __restrict__ beta,
                                              const float* __restrict__ mean,
                                              const float* __restrict__ var,
                                              int n) {
    int warp = (blockIdx.x * blockDim.x + threadIdx.x) >> 5;
    int lane = threadIdx.x & 31;
    if (warp >= n) return;

    int node = warp;
    int start = g_off[node];
    int end   = start + g_degi[node];

    float4 acc0 = make_float4(0.f, 0.f, 0.f, 0.f);
    float4 acc1 = make_float4(0.f, 0.f, 0.f, 0.f);

    int e = start;
    for (; e + 3 < end; e += 4) {
        int s0 = g_csr[e + 0], s1 = g_csr[e + 1];
        int s2 = g_csr[e + 2], s3 = g_csr[e + 3];
        float w0 = g_dinv[s0], w1 = g_dinv[s1];
        float w2 = g_dinv[s2], w3 = g_dinv[s3];
        const float4* r0 = (const float4*)(g_h + (size_t)s0 * DOUT);
        const float4* r1 = (const float4*)(g_h + (size_t)s1 * DOUT);
        const float4* r2 = (const float4*)(g_h + (size_t)s2 * DOUT);
        const float4* r3 = (const float4*)(g_h + (size_t)s3 * DOUT);
        float4 a0 = __ldg(r0 + lane),      a1 = __ldg(r0 + lane + 32);
        float4 b0 = __ldg(r1 + lane),      b1 = __ldg(r1 + lane + 32);
        float4 c0 = __ldg(r2 + lane),      c1 = __ldg(r2 + lane + 32);
        float4 d0 = __ldg(r3 + lane),      d1 = __ldg(r3 + lane + 32);
        FMA4(acc0, a0, w0); FMA4(acc1, a1, w0);
        FMA4(acc0, b0, w1); FMA4(acc1, b1, w1);
        FMA4(acc0, c0, w2); FMA4(acc1, c1, w2);
        FMA4(acc0, d0, w3); FMA4(acc1, d1, w3);
    }
    for (; e < end; e++) {
        int s0 = g_csr[e];
        float w0 = g_dinv[s0];
        const float4* r0 = (const float4*)(g_h + (size_t)s0 * DOUT);
        float4 a0 = __ldg(r0 + lane), a1 = __ldg(r0 + lane + 32);
        FMA4(acc0, a0, w0); FMA4(acc1, a1, w0);
    }

    float di = g_dinv[node];
    const float4* hr = (const float4*)(g_h + (size_t)node * DOUT);
    float4 h0 = __ldg(hr + lane), h1 = __ldg(hr + lane + 32);
    FMA4(acc0, h0, di); FMA4(acc1, h1, di);
    acc0.x *= di; acc0.y *= di; acc0.z *= di; acc0.w *= di;
    acc1.x *= di; acc1.y *= di; acc1.z *= di; acc1.w *= di;

    #pragma unroll
    for (int half = 0; half < 2; half++) {
        int c4 = lane + half * 32;
        float4 bv = ((const float4*)b)[c4];
        float4 gv = ((const float4*)gamma)[c4];
        float4 tv = ((const float4*)beta)[c4];
        float4 mv = ((const float4*)mean)[c4];
        float4 vv = ((const float4*)var)[c4];
        float4 a = half ? acc1 : acc0;
        float4 r;
        float sx = gv.x * rsqrtf(vv.x + 1e-5f);
        float sy = gv.y * rsqrtf(vv.y + 1e-5f);
        float sz = gv.z * rsqrtf(vv.z + 1e-5f);
        float sw = gv.w * rsqrtf(vv.w + 1e-5f);
        r.x = fmaxf(fmaf(a.x + bv.x - mv.x, sx, tv.x), 0.f);
        r.y = fmaxf(fmaf(a.y + bv.y - mv.y, sy, tv.y), 0.f);
        r.z = fmaxf(fmaf(a.z + bv.z - mv.z, sz, tv.z), 0.f);
        r.w = fmaxf(fmaf(a.w + bv.w - mv.w, sw, tv.w), 0.f);
        ((float4*)(out + (size_t)node * DOUT))[c4] = r;
    }
}

// ---------------------------------------------------------------------------
// Two-stream DAG:
//   main:  wt -> gemm -----------------------------------+-> node
//   s2:    zero -> count -> scan1/2/3 -> fill -----------+
// ---------------------------------------------------------------------------
extern "C" void kernel_launch(void* const* d_in, const int* in_sizes, int n_in,
                              void* d_out, int out_size) {
    const float* x      = (const float*)d_in[0];
    const int*   ei     = (const int*)d_in[1];   // int32 (jax x64 disabled)
    const float* W      = (const float*)d_in[2];
    const float* b      = (const float*)d_in[3];
    const float* gamma  = (const float*)d_in[4];
    const float* beta   = (const float*)d_in[5];
    const float* rmean  = (const float*)d_in[6];
    const float* rvar   = (const float*)d_in[7];
    float* out = (float*)d_out;

    int N = in_sizes[0] / DIN;     // 50000
    int E = in_sizes[1] / 2;       // 800000
    const int* src = ei;
    const int* dst = ei + E;
    int nb = (N + 1023) / 1024;

    static cudaStream_t s2;
    static cudaEvent_t ev_fork, ev_join;
    static bool init_done = false;
    if (!init_done) {
        cudaFuncSetAttribute(k_gemm_wmma,
                             cudaFuncAttributeMaxDynamicSharedMemorySize,
                             SMEM_BYTES);
        cudaStreamCreateWithFlags(&s2, cudaStreamNonBlocking);
        cudaEventCreateWithFlags(&ev_fork, cudaEventDisableTiming);
        cudaEventCreateWithFlags(&ev_join, cudaEventDisableTiming);
        init_done = true;
    }

    // fork
    cudaEventRecord(ev_fork, 0);
    cudaStreamWaitEvent(s2, ev_fork, 0);

    k_wt<<<(DIN * DOUT + 255) / 256, 256>>>(W);                    // launch 1
    k_zero<<<(N + 255) / 256, 256, 0, s2>>>(N);                    // launch 2
    k_count<<<(E + 255) / 256, 256, 0, s2>>>(dst, E);              // launch 3

    dim3 ggrid(MPAD / 128, DOUT / 128);
    k_gemm_wmma<<<ggrid, 256, SMEM_BYTES>>>(x, N);                 // launch 4

    k_scan1<<<nb, 1024, 0, s2>>>(N);
    k_scan2<<<1, 64, 0, s2>>>(nb);
    k_scan3<<<nb, 1024, 0, s2>>>(N);
    k_fill<<<(E + 255) / 256, 256, 0, s2>>>(src, dst, E);

    // join
    cudaEventRecord(ev_join, s2);
    cudaStreamWaitEvent(0, ev_join, 0);

    long long nthreads = (long long)N * 32;
    k_node<<<(int)((nthreads + 255) / 256), 256>>>(out, b, gamma, beta,
                                                   rmean, rvar, N);
}